// round 4
// baseline (speedup 1.0000x reference)
#include <cuda_runtime.h>
#include <math.h>

#define SEQ    2048
#define BATCH  2
#define NEMBD  1024
#define NHEAD  16
#define HDIM   64
#define WINDOW 256
#define QSCALE 0.125f          // 1/sqrt(64)
#define MROWS  (BATCH*SEQ)     // 4096
#define MASKV  (-10000.0f)

typedef unsigned long long u64;

// ---- packed f32x2 helpers (SASS FFMA2 path; ptxas never emits from C++) ----
__device__ __forceinline__ u64 splat2(float x) {
    u64 r; asm("mov.b64 %0, {%1, %1};" : "=l"(r) : "f"(x)); return r;
}
__device__ __forceinline__ void fma2(u64& d, u64 a, u64 b) {
    asm("fma.rn.f32x2 %0, %1, %2, %0;" : "+l"(d) : "l"(a), "l"(b));
}
__device__ __forceinline__ u64 mul2(u64 a, u64 b) {
    u64 d; asm("mul.rn.f32x2 %0, %1, %2;" : "=l"(d) : "l"(a), "l"(b)); return d;
}
__device__ __forceinline__ void unpk2(u64 a, float& lo, float& hi) {
    asm("mov.b64 {%0, %1}, %2;" : "=f"(lo), "=f"(hi) : "l"(a));
}

// Scratch (device globals: allocation-free per harness rules)
__device__ float g_qkv[(size_t)MROWS * 3 * NEMBD];   // [4096, 3072]
__device__ float g_attn[(size_t)MROWS * NEMBD];      // [4096, 1024]

// ---------------------------------------------------------------------------
// Register-blocked SGEMM with packed f32x2 FMA + double-buffered SMEM.
// C[M,N] = A[M,K] @ B[K,N] + bias[N]. BM=BN=128, BK=16, 256 thr, 8x8 utile.
// ---------------------------------------------------------------------------
template<int N_, int K_>
__global__ __launch_bounds__(256) void sgemm_bias(const float* __restrict__ A,
                                                  const float* __restrict__ B,
                                                  const float* __restrict__ bias,
                                                  float* __restrict__ C) {
    __shared__ float As[2][16][132];   // As[buf][k][m], padded
    __shared__ float Bs[2][16][128];   // Bs[buf][k][n]

    const int m0 = blockIdx.y * 128;
    const int n0 = blockIdx.x * 128;
    const int tid = threadIdx.x;
    const int tx = tid & 15;
    const int ty = tid >> 4;

    // per-thread load coordinates
    const int am0 = tid >> 2;            // A row for chunk 0
    const int am1 = (tid + 256) >> 2;    // A row for chunk 1
    const int ak4 = (tid & 3) * 4;       // A k offset
    const int bk0 = tid >> 5;
    const int bk1 = (tid + 256) >> 5;
    const int bn4 = (tid & 31) * 4;

    float4 aR0, aR1, bR0, bR1;

    auto gload = [&](int k0) {
        aR0 = *(const float4*)(A + (size_t)(m0 + am0) * K_ + k0 + ak4);
        aR1 = *(const float4*)(A + (size_t)(m0 + am1) * K_ + k0 + ak4);
        bR0 = *(const float4*)(B + (size_t)(k0 + bk0) * N_ + n0 + bn4);
        bR1 = *(const float4*)(B + (size_t)(k0 + bk1) * N_ + n0 + bn4);
    };
    auto sstore = [&](int buf) {
        As[buf][ak4 + 0][am0] = aR0.x;
        As[buf][ak4 + 1][am0] = aR0.y;
        As[buf][ak4 + 2][am0] = aR0.z;
        As[buf][ak4 + 3][am0] = aR0.w;
        As[buf][ak4 + 0][am1] = aR1.x;
        As[buf][ak4 + 1][am1] = aR1.y;
        As[buf][ak4 + 2][am1] = aR1.z;
        As[buf][ak4 + 3][am1] = aR1.w;
        *(float4*)&Bs[buf][bk0][bn4] = bR0;
        *(float4*)&Bs[buf][bk1][bn4] = bR1;
    };

    u64 acc2[8][4];
#pragma unroll
    for (int i = 0; i < 8; i++)
#pragma unroll
        for (int j = 0; j < 4; j++) acc2[i][j] = 0ull;

    gload(0);
    sstore(0);
    __syncthreads();

    int buf = 0;
    for (int k0 = 0; k0 < K_; k0 += 16) {
        const bool more = (k0 + 16) < K_;
        if (more) gload(k0 + 16);

#pragma unroll
        for (int k = 0; k < 16; k++) {
            float a[8];
            *(float4*)&a[0] = *(float4*)&As[buf][k][ty * 8];
            *(float4*)&a[4] = *(float4*)&As[buf][k][ty * 8 + 4];
            union { float4 v[2]; u64 p[4]; } bu;
            bu.v[0] = *(float4*)&Bs[buf][k][tx * 8];
            bu.v[1] = *(float4*)&Bs[buf][k][tx * 8 + 4];
#pragma unroll
            for (int i = 0; i < 8; i++) {
                const u64 as = splat2(a[i]);
#pragma unroll
                for (int j = 0; j < 4; j++) fma2(acc2[i][j], as, bu.p[j]);
            }
        }

        if (more) sstore(buf ^ 1);
        __syncthreads();
        buf ^= 1;
    }

    // epilogue: + bias, write C
    const int ncol = n0 + tx * 8;
    float bb[8];
    *(float4*)&bb[0] = *(const float4*)(bias + ncol);
    *(float4*)&bb[4] = *(const float4*)(bias + ncol + 4);
#pragma unroll
    for (int i = 0; i < 8; i++) {
        const int m = m0 + ty * 8 + i;
        float o[8];
#pragma unroll
        for (int j = 0; j < 4; j++) unpk2(acc2[i][j], o[j * 2], o[j * 2 + 1]);
        float4 v0, v1;
        v0.x = o[0] + bb[0]; v0.y = o[1] + bb[1]; v0.z = o[2] + bb[2]; v0.w = o[3] + bb[3];
        v1.x = o[4] + bb[4]; v1.y = o[5] + bb[5]; v1.z = o[6] + bb[6]; v1.w = o[7] + bb[7];
        *(float4*)(C + (size_t)m * N_ + ncol) = v0;
        *(float4*)(C + (size_t)m * N_ + ncol + 4) = v1;
    }
}

// ---------------------------------------------------------------------------
// Sliding-window causal flash attention with f32x2 inner products.
// One block per (64-query tile, head, batch). 256 threads = 16x16,
// 4x4 micro-tile on the 64x64 score tile. Online softmax.
// ---------------------------------------------------------------------------
__global__ __launch_bounds__(256) void attn_kernel(const float* __restrict__ qkv,
                                                   float* __restrict__ out) {
    extern __shared__ float sm[];
    float(*Qs)[68] = (float(*)[68])(sm);              // Qs[d][m] (transposed)
    float(*Ks)[68] = (float(*)[68])(sm + 64 * 68);    // Ks[d][n] (transposed)
    float(*Vs)[68] = (float(*)[68])(sm + 2 * 64 * 68);// Vs[n][d] (natural)
    float(*Ps)[68] = (float(*)[68])(sm + 3 * 64 * 68);// Ps[m][n] (natural)

    const int q0 = blockIdx.x * 64;
    const int h  = blockIdx.y;
    const int b  = blockIdx.z;
    const int tid = threadIdx.x;
    const int tx = tid & 15;
    const int ty = tid >> 4;

    const float* qb = qkv + (size_t)b * SEQ * 3072 + h * 64;
    const float* kb = qb + 1024;
    const float* vb = qb + 2048;

    // Load Q tile (64x64) transposed into Qs[d][m]
#pragma unroll
    for (int it = 0; it < 4; it++) {
        int i  = tid + it * 256;
        int m  = i >> 4;
        int d4 = (i & 15) * 4;
        float4 v = *(const float4*)(qb + (size_t)(q0 + m) * 3072 + d4);
        Qs[d4 + 0][m] = v.x;
        Qs[d4 + 1][m] = v.y;
        Qs[d4 + 2][m] = v.z;
        Qs[d4 + 3][m] = v.w;
    }

    u64 o2[4][2];
#pragma unroll
    for (int i = 0; i < 4; i++) { o2[i][0] = 0ull; o2[i][1] = 0ull; }
    float mrow[4], lrow[4];
#pragma unroll
    for (int i = 0; i < 4; i++) { mrow[i] = -1e30f; lrow[i] = 0.f; }

    int jlo = q0 - (WINDOW - 1);
    if (jlo < 0) jlo = 0;
    const int kt_first = (jlo / 64) * 64;

    for (int kt = kt_first; kt <= q0; kt += 64) {
        __syncthreads();   // previous tile's Ks/Vs/Ps fully consumed

        // Load K (transposed) and V (natural) tiles
#pragma unroll
        for (int it = 0; it < 4; it++) {
            int i  = tid + it * 256;
            int n  = i >> 4;
            int d4 = (i & 15) * 4;
            float4 kv = *(const float4*)(kb + (size_t)(kt + n) * 3072 + d4);
            Ks[d4 + 0][n] = kv.x;
            Ks[d4 + 1][n] = kv.y;
            Ks[d4 + 2][n] = kv.z;
            Ks[d4 + 3][n] = kv.w;
            *(float4*)&Vs[n][d4] = *(const float4*)(vb + (size_t)(kt + n) * 3072 + d4);
        }
        __syncthreads();

        // S = Q @ K^T  (pairs over score columns)
        u64 s2[4][2];
#pragma unroll
        for (int i = 0; i < 4; i++) { s2[i][0] = 0ull; s2[i][1] = 0ull; }

#pragma unroll 8
        for (int d = 0; d < 64; d++) {
            float a[4];
            *(float4*)a = *(float4*)&Qs[d][ty * 4];
            union { float4 v; u64 p[2]; } kk;
            kk.v = *(float4*)&Ks[d][tx * 4];
#pragma unroll
            for (int i = 0; i < 4; i++) {
                const u64 as = splat2(a[i]);
                fma2(s2[i][0], as, kk.p[0]);
                fma2(s2[i][1], as, kk.p[1]);
            }
        }

        float s[4][4];
#pragma unroll
        for (int i = 0; i < 4; i++) {
            unpk2(s2[i][0], s[i][0], s[i][1]);
            unpk2(s2[i][1], s[i][2], s[i][3]);
        }

        // scale + sliding-window causal mask
#pragma unroll
        for (int i = 0; i < 4; i++) {
            const int gi = q0 + ty * 4 + i;
#pragma unroll
            for (int j = 0; j < 4; j++) {
                const int gj = kt + tx * 4 + j;
                const bool ok = (gj <= gi) && (gj > gi - WINDOW);
                s[i][j] = ok ? s[i][j] * QSCALE : MASKV;
            }
        }

        // online softmax per row (reduce over the 16 tx lanes)
#pragma unroll
        for (int i = 0; i < 4; i++) {
            float tmax = fmaxf(fmaxf(s[i][0], s[i][1]), fmaxf(s[i][2], s[i][3]));
#pragma unroll
            for (int o = 1; o < 16; o <<= 1)
                tmax = fmaxf(tmax, __shfl_xor_sync(0xffffffffu, tmax, o));
            const float mnew = fmaxf(mrow[i], tmax);
            const float corr = __expf(mrow[i] - mnew);
            mrow[i] = mnew;
            float rs = 0.f;
#pragma unroll
            for (int j = 0; j < 4; j++) {
                const float p = __expf(s[i][j] - mnew);
                s[i][j] = p;
                rs += p;
            }
#pragma unroll
            for (int o = 1; o < 16; o <<= 1)
                rs += __shfl_xor_sync(0xffffffffu, rs, o);
            lrow[i] = lrow[i] * corr + rs;
            const u64 c2 = splat2(corr);
            o2[i][0] = mul2(o2[i][0], c2);
            o2[i][1] = mul2(o2[i][1], c2);
        }

        // stage P (natural layout, conflict-free float4 stores)
#pragma unroll
        for (int i = 0; i < 4; i++) {
            float4 pv = make_float4(s[i][0], s[i][1], s[i][2], s[i][3]);
            *(float4*)&Ps[ty * 4 + i][tx * 4] = pv;
        }
        __syncthreads();

        // O += P @ V (f32x2, vectorized Ps reads)
#pragma unroll 4
        for (int n0 = 0; n0 < 64; n0 += 4) {
            float pa[4][4];
#pragma unroll
            for (int i = 0; i < 4; i++)
                *(float4*)pa[i] = *(float4*)&Ps[ty * 4 + i][n0];
#pragma unroll
            for (int nn = 0; nn < 4; nn++) {
                union { float4 v; u64 p[2]; } vv;
                vv.v = *(float4*)&Vs[n0 + nn][tx * 4];
#pragma unroll
                for (int i = 0; i < 4; i++) {
                    const u64 as = splat2(pa[i][nn]);
                    fma2(o2[i][0], as, vv.p[0]);
                    fma2(o2[i][1], as, vv.p[1]);
                }
            }
        }
    }

    // finalize + write: out[b*T + t][h*64 + d]
#pragma unroll
    for (int i = 0; i < 4; i++) {
        const float inv = 1.0f / lrow[i];
        float o[4];
        unpk2(o2[i][0], o[0], o[1]);
        unpk2(o2[i][1], o[2], o[3]);
        float4 v;
        v.x = o[0] * inv; v.y = o[1] * inv; v.z = o[2] * inv; v.w = o[3] * inv;
        *(float4*)(out + (size_t)(b * SEQ + q0 + ty * 4 + i) * NEMBD + h * 64 + tx * 4) = v;
    }
}

// ---------------------------------------------------------------------------

static const size_t ATTN_SMEM = 4 * 64 * 68 * sizeof(float);  // 69632 B

extern "C" void kernel_launch(void* const* d_in, const int* in_sizes, int n_in,
                              void* d_out, int out_size) {
    const float* x      = (const float*)d_in[0];   // [2,2048,1024]
    const float* w_attn = (const float*)d_in[1];   // [1024,3072]
    const float* b_attn = (const float*)d_in[2];   // [3072]
    const float* w_proj = (const float*)d_in[3];   // [1024,1024]
    const float* b_proj = (const float*)d_in[4];   // [1024]
    float* out = (float*)d_out;                    // [2,2048,1024]

    float* qkv;  cudaGetSymbolAddress((void**)&qkv,  g_qkv);
    float* attn; cudaGetSymbolAddress((void**)&attn, g_attn);

    cudaFuncSetAttribute(attn_kernel, cudaFuncAttributeMaxDynamicSharedMemorySize,
                         (int)ATTN_SMEM);

    // 1) QKV projection: [4096,1024] @ [1024,3072] + b_attn
    sgemm_bias<3 * NEMBD, NEMBD><<<dim3(3 * NEMBD / 128, MROWS / 128), 256>>>(
        x, w_attn, b_attn, qkv);

    // 2) sliding-window attention -> g_attn [4096,1024]
    attn_kernel<<<dim3(SEQ / 64, NHEAD, BATCH), 256, ATTN_SMEM>>>(qkv, attn);

    // 3) output projection: [4096,1024] @ [1024,1024] + b_proj
    sgemm_bias<NEMBD, NEMBD><<<dim3(NEMBD / 128, MROWS / 128), 256>>>(
        attn, w_proj, b_proj, out);
}